// round 3
// baseline (speedup 1.0000x reference)
#include <cuda_runtime.h>
#include <math.h>

// Problem constants
#define BATCH 8
#define HW 56
#define NPIX (HW*HW)        // 3136
#define CMID 32
#define CXV 512             // cout*8
#define CU 256              // cmid*8
#define KIN 512             // GEMM K (cin*8)
#define MROWS 768           // 512 xv rows + 256 u rows

// Scratch (device globals; no allocation allowed)
__device__ float g_W[MROWS * KIN];                 // expanded weights, row-major [m][k]
__device__ float g_xv[(size_t)BATCH * CXV * NPIX]; // value branch
__device__ float g_u[(size_t)BATCH * CU * NPIX];   // pre-GN dyn branch
__device__ float g_mean[BATCH * CMID];
__device__ float g_rstd[BATCH * CMID];

__constant__ int c_perm[8][8] = {
    {0, 1, 2, 3, 4, 5, 6, 7},
    {3, 0, 1, 2, 5, 6, 7, 4},
    {2, 3, 0, 1, 6, 7, 4, 5},
    {1, 2, 3, 0, 7, 4, 5, 6},
    {4, 5, 6, 7, 0, 1, 2, 3},
    {5, 6, 7, 4, 3, 0, 1, 2},
    {6, 7, 4, 5, 2, 3, 0, 1},
    {7, 4, 5, 6, 1, 2, 3, 0},
};

// source tap index (into wgt's 9 taps) for output tap t, per group element f
__constant__ int c_tap[8][9] = {
    {0,1,2,3,4,5,6,7,8},
    {2,5,8,1,4,7,0,3,6},
    {8,7,6,5,4,3,2,1,0},
    {6,3,0,7,4,1,8,5,2},
    {2,1,0,5,4,3,8,7,6},
    {8,5,2,7,4,1,6,3,0},
    {6,7,8,3,4,5,0,1,2},
    {0,3,6,1,4,7,2,5,8},
};

// packed f32x2 helpers
static __device__ __forceinline__ unsigned long long pack2(float v) {
    unsigned long long r;
    asm("mov.b64 %0, {%1, %1};" : "=l"(r) : "f"(v));
    return r;
}
static __device__ __forceinline__ void fma2(unsigned long long& d,
                                            unsigned long long a,
                                            unsigned long long b) {
    asm("fma.rn.f32x2 %0, %1, %2, %0;" : "+l"(d) : "l"(a), "l"(b));
}
static __device__ __forceinline__ void unpack2(unsigned long long v, float& lo, float& hi) {
    asm("mov.b64 {%0, %1}, %2;" : "=f"(lo), "=f"(hi) : "l"(v));
}

// ---------------------------------------------------------------------------
// Kernel 0: expand base weights into full 768x512 GEMM matrix
// ---------------------------------------------------------------------------
__global__ void expand_w_kernel(const float* __restrict__ w_v,
                                const float* __restrict__ w1) {
    int idx = blockIdx.x * 256 + threadIdx.x;
    if (idx >= MROWS * KIN) return;
    int m = idx / KIN, kk = idx - m * KIN;
    int i = kk >> 3, f = kk & 7;
    float val;
    if (m < 512) {
        int o = m >> 3, g = m & 7;
        val = w_v[(o * 64 + i) * 8 + c_perm[g][f]];
    } else {
        int m2 = m - 512;
        int o = m2 >> 3, g = m2 & 7;
        val = w1[(o * 64 + i) * 8 + c_perm[g][f]];
    }
    g_W[idx] = val;
}

// ---------------------------------------------------------------------------
// Kernel 1: SGEMM  C[768 x 3136] = W[768 x 512] * x_b[512 x 3136], per batch
// 128 threads, block tile 128(M) x 64(N), BK=16, 8x8 per-thread microtile,
// inner product via packed fma.rn.f32x2 (FFMA2).
// ---------------------------------------------------------------------------
__global__ __launch_bounds__(128) void gemm_kernel(const float* __restrict__ x) {
    const int bn = blockIdx.x;    // 0..48
    const int bm = blockIdx.y;    // 0..5
    const int bb = blockIdx.z;    // batch

    __shared__ float As[16][132]; // [k][m], padded
    __shared__ float Bs[16][64];  // [k][n]

    const int tid = threadIdx.x;
    const int tx = tid & 7;       // N dir: 8 cols each
    const int ty = tid >> 3;      // M dir: 0..15, 8 rows each

    const float* __restrict__ Bbase = x + (size_t)bb * KIN * NPIX + bn * 64;
    const float* __restrict__ Abase = g_W + (size_t)bm * 128 * KIN;

    // A loads: thread tid owns row m=tid, 16 k per iter (4x float4)
    // B loads: krow = tid>>4 (0..7) and +8, ncol = (tid&15)*4 (float4)
    const int b_k = tid >> 4;
    const int b_n = (tid & 15) * 4;

    unsigned long long acc2[8][4];
#pragma unroll
    for (int r = 0; r < 8; r++)
#pragma unroll
        for (int c = 0; c < 4; c++) acc2[r][c] = 0ull;

    for (int k0 = 0; k0 < KIN; k0 += 16) {
        float4 av[4];
#pragma unroll
        for (int j = 0; j < 4; j++)
            av[j] = *(const float4*)(Abase + (size_t)tid * KIN + k0 + j * 4);
        float4 bv0 = *(const float4*)(Bbase + (size_t)(k0 + b_k) * NPIX + b_n);
        float4 bv1 = *(const float4*)(Bbase + (size_t)(k0 + 8 + b_k) * NPIX + b_n);

        __syncthreads();
#pragma unroll
        for (int j = 0; j < 4; j++) {
            As[j * 4 + 0][tid] = av[j].x;
            As[j * 4 + 1][tid] = av[j].y;
            As[j * 4 + 2][tid] = av[j].z;
            As[j * 4 + 3][tid] = av[j].w;
        }
        *(float4*)&Bs[b_k][b_n] = bv0;
        *(float4*)&Bs[b_k + 8][b_n] = bv1;
        __syncthreads();

#pragma unroll
        for (int k = 0; k < 16; k++) {
            float4 a0 = *(const float4*)&As[k][ty * 8];
            float4 a1 = *(const float4*)&As[k][ty * 8 + 4];
            unsigned long long bp[4];
#pragma unroll
            for (int c = 0; c < 4; c++)
                bp[c] = *(const unsigned long long*)&Bs[k][tx * 8 + c * 2];
            unsigned long long am2[8];
            am2[0] = pack2(a0.x); am2[1] = pack2(a0.y);
            am2[2] = pack2(a0.z); am2[3] = pack2(a0.w);
            am2[4] = pack2(a1.x); am2[5] = pack2(a1.y);
            am2[6] = pack2(a1.z); am2[7] = pack2(a1.w);
#pragma unroll
            for (int r = 0; r < 8; r++)
#pragma unroll
                for (int c = 0; c < 4; c++)
                    fma2(acc2[r][c], am2[r], bp[c]);
        }
    }

    // write out: rows bm*128 + ty*8 + r, cols bn*64 + tx*8 .. +7
    const int n_global = bn * 64 + tx * 8;
    const bool to_xv = (bm < 4);
#pragma unroll
    for (int r = 0; r < 8; r++) {
        float v[8];
#pragma unroll
        for (int c = 0; c < 4; c++) unpack2(acc2[r][c], v[2 * c], v[2 * c + 1]);
        float4 lo = make_float4(v[0], v[1], v[2], v[3]);
        float4 hi = make_float4(v[4], v[5], v[6], v[7]);
        if (to_xv) {
            int m_global = bm * 128 + ty * 8 + r;
            float* dst = &g_xv[((size_t)bb * CXV + m_global) * NPIX + n_global];
            *(float4*)dst = lo;
            *(float4*)(dst + 4) = hi;
        } else {
            int m_global = (bm - 4) * 128 + ty * 8 + r;
            float* dst = &g_u[((size_t)bb * CU + m_global) * NPIX + n_global];
            *(float4*)dst = lo;
            *(float4*)(dst + 4) = hi;
        }
    }
}

// ---------------------------------------------------------------------------
// Kernel 2: GroupNorm stats. One block per (b, i) pair; reduce over 8*3136 vals
// ---------------------------------------------------------------------------
__global__ __launch_bounds__(256) void stats_kernel() {
    const int bi = blockIdx.x;        // b*32 + i
    const int b = bi >> 5, i = bi & 31;
    const float* __restrict__ base = g_u + ((size_t)b * CU + i * 8) * NPIX;
    const int n = 8 * NPIX;           // 25088

    float s = 0.f, s2 = 0.f;
    for (int idx = threadIdx.x; idx < n; idx += 256) {
        float v = base[idx];
        s += v;
        s2 += v * v;
    }
    __shared__ float ss[256], ss2[256];
    ss[threadIdx.x] = s;
    ss2[threadIdx.x] = s2;
    __syncthreads();
    for (int stride = 128; stride > 0; stride >>= 1) {
        if (threadIdx.x < stride) {
            ss[threadIdx.x] += ss[threadIdx.x + stride];
            ss2[threadIdx.x] += ss2[threadIdx.x + stride];
        }
        __syncthreads();
    }
    if (threadIdx.x == 0) {
        float mean = ss[0] / (float)n;
        float var = ss2[0] / (float)n - mean * mean;
        g_mean[bi] = mean;
        g_rstd[bi] = rsqrtf(var + 1e-5f);
    }
}

// ---------------------------------------------------------------------------
// Kernel 3: epilogue. One block = (b, f, G, 14x14 spatial tile).
// Phase A: per-pixel theta[9] = w2[G] @ relu(GN(u[:, f-slice])) + b2[G]
// Phase B: one thread per pixel, 9 thetas in regs, loop 16 channels.
// ---------------------------------------------------------------------------
__global__ __launch_bounds__(256) void epi_kernel(const float* __restrict__ gn_gamma,
                                                  const float* __restrict__ gn_beta,
                                                  const float* __restrict__ w2,
                                                  const float* __restrict__ b2,
                                                  float* __restrict__ out) {
    const int tile = blockIdx.x;          // 0..15
    const int gf = blockIdx.y;            // f*4 + G
    const int bb = blockIdx.z;
    const int f = gf >> 2, G = gf & 3;
    const int ty0 = (tile >> 2) * 14;
    const int tx0 = (tile & 3) * 14;
    const int tid = threadIdx.x;

    __shared__ float xs[16][16][17];      // [c][yy][xx], padded
    __shared__ float th[9][200];          // theta by SOURCE tap, per pixel (196)
    __shared__ float s_w2[9][32];
    __shared__ float s_b2[9];
    __shared__ float s_gn[32][4];         // mean, rstd, gamma, beta per i

    for (int idx = tid; idx < 9 * 32; idx += 256) {
        int t = idx >> 5, i = idx & 31;
        s_w2[t][i] = w2[(G * 9 + t) * 32 + i];
    }
    if (tid < 9) s_b2[tid] = b2[G * 9 + tid];
    if (tid >= 32 && tid < 64) {
        int i = tid - 32;
        s_gn[i][0] = g_mean[bb * 32 + i];
        s_gn[i][1] = g_rstd[bb * 32 + i];
        s_gn[i][2] = gn_gamma[i * 8 + f];
        s_gn[i][3] = gn_beta[i * 8 + f];
    }

    // load padded xv tile (16 channels x 16x16)
    {
        int yy = tid >> 4, xx = tid & 15;
        int gy = ty0 - 1 + yy, gx = tx0 - 1 + xx;
        bool ok = (gy >= 0 && gy < HW && gx >= 0 && gx < HW);
        size_t base = ((size_t)bb * CXV + G * 128 + f) * NPIX + gy * HW + gx;
#pragma unroll
        for (int c = 0; c < 16; c++) {
            float v = 0.f;
            if (ok) v = g_xv[base + (size_t)c * 8 * NPIX];
            xs[c][yy][xx] = v;
        }
    }
    __syncthreads();

    if (tid < 196) {
        int py = tid / 14, px = tid - py * 14;
        int p = (ty0 + py) * HW + (tx0 + px);
        float acc[9];
#pragma unroll
        for (int t = 0; t < 9; t++) acc[t] = s_b2[t];
        const float* __restrict__ ub = g_u + ((size_t)bb * CU + f) * NPIX + p;
#pragma unroll 8
        for (int i = 0; i < 32; i++) {
            float v = ub[(size_t)i * 8 * NPIX];
            v = (v - s_gn[i][0]) * s_gn[i][1] * s_gn[i][2] + s_gn[i][3];
            v = fmaxf(v, 0.f);
#pragma unroll
            for (int t = 0; t < 9; t++) acc[t] = fmaf(s_w2[t][i], v, acc[t]);
        }
#pragma unroll
        for (int t = 0; t < 9; t++) th[t][tid] = acc[t];
    }
    __syncthreads();

    // Phase B: one thread per pixel; permuted thetas live in registers.
    if (tid < 196) {
        int py = tid / 14, px = tid - py * 14;
        float thr[9];
#pragma unroll
        for (int t = 0; t < 9; t++) thr[t] = th[c_tap[f][t]][tid];
        size_t obase = ((size_t)bb * CXV + G * 128 + f) * NPIX
                     + (ty0 + py) * HW + (tx0 + px);
#pragma unroll
        for (int c = 0; c < 16; c++) {
            float acc = 0.f;
#pragma unroll
            for (int ti = 0; ti < 3; ti++)
#pragma unroll
                for (int tj = 0; tj < 3; tj++)
                    acc = fmaf(thr[ti * 3 + tj], xs[c][py + ti][px + tj], acc);
            out[obase + (size_t)c * 8 * NPIX] = acc;
        }
    }
}

// ---------------------------------------------------------------------------
extern "C" void kernel_launch(void* const* d_in, const int* in_sizes, int n_in,
                              void* d_out, int out_size) {
    const float* x        = (const float*)d_in[0];
    const float* w_v      = (const float*)d_in[1];
    const float* w1       = (const float*)d_in[2];
    const float* gn_gamma = (const float*)d_in[3];
    const float* gn_beta  = (const float*)d_in[4];
    const float* w2       = (const float*)d_in[5];
    const float* b2       = (const float*)d_in[6];
    float* out = (float*)d_out;

    expand_w_kernel<<<(MROWS * KIN + 255) / 256, 256>>>(w_v, w1);
    {
        dim3 grid(NPIX / 64, MROWS / 128, BATCH);   // (49, 6, 8)
        gemm_kernel<<<grid, 128>>>(x);
    }
    stats_kernel<<<BATCH * CMID, 256>>>();
    {
        dim3 grid(16, 32, BATCH);                   // (tiles, f*4+G, b)
        epi_kernel<<<grid, 256>>>(gn_gamma, gn_beta, w2, b2, out);
    }
}

// round 5
// speedup vs baseline: 1.7914x; 1.7914x over previous
#include <cuda_runtime.h>
#include <cuda_bf16.h>
#include <math.h>
#include <stdint.h>

// Problem constants
#define BATCH 8
#define HW 56
#define NPIX 3136
#define CMID 32
#define CXV 512             // cout*8
#define CU 256              // cmid*8
#define KIN 512             // GEMM K
#define MROWS 768           // 512 xv + 256 u

// ---- device scratch (no allocation allowed) ----
__device__ __nv_bfloat16 g_Wh[MROWS * KIN];                // [m][k] row-major, hi
__device__ __nv_bfloat16 g_Wl[MROWS * KIN];                // lo
__device__ __nv_bfloat16 g_xh[(size_t)BATCH * NPIX * KIN]; // [b][n][k], hi
__device__ __nv_bfloat16 g_xl[(size_t)BATCH * NPIX * KIN]; // lo
__device__ float g_xv[(size_t)BATCH * CXV * NPIX];
__device__ float g_u[(size_t)BATCH * CU * NPIX];
__device__ float g_mean[BATCH * CMID];
__device__ float g_rstd[BATCH * CMID];

__constant__ int c_perm[8][8] = {
    {0, 1, 2, 3, 4, 5, 6, 7},
    {3, 0, 1, 2, 5, 6, 7, 4},
    {2, 3, 0, 1, 6, 7, 4, 5},
    {1, 2, 3, 0, 7, 4, 5, 6},
    {4, 5, 6, 7, 0, 1, 2, 3},
    {5, 6, 7, 4, 3, 0, 1, 2},
    {6, 7, 4, 5, 2, 3, 0, 1},
    {7, 4, 5, 6, 1, 2, 3, 0},
};
__constant__ int c_tap[8][9] = {
    {0,1,2,3,4,5,6,7,8},
    {2,5,8,1,4,7,0,3,6},
    {8,7,6,5,4,3,2,1,0},
    {6,3,0,7,4,1,8,5,2},
    {2,1,0,5,4,3,8,7,6},
    {8,5,2,7,4,1,6,3,0},
    {6,7,8,3,4,5,0,1,2},
    {0,3,6,1,4,7,2,5,8},
};

__device__ __forceinline__ uint32_t smem_u32(const void* p) {
    uint32_t a;
    asm("{ .reg .u64 t; cvta.to.shared.u64 t, %1; cvt.u32.u64 %0, t; }" : "=r"(a) : "l"(p));
    return a;
}
__device__ __forceinline__ void ldsm_x4(uint32_t* r, uint32_t addr) {
    asm volatile("ldmatrix.sync.aligned.m8n8.x4.shared.b16 {%0,%1,%2,%3}, [%4];"
                 : "=r"(r[0]), "=r"(r[1]), "=r"(r[2]), "=r"(r[3]) : "r"(addr));
}
__device__ __forceinline__ void mma16816(float* c, const uint32_t* a, const uint32_t* b) {
    asm volatile("mma.sync.aligned.m16n8k16.row.col.f32.bf16.bf16.f32 "
                 "{%0,%1,%2,%3}, {%4,%5,%6,%7}, {%8,%9}, {%0,%1,%2,%3};"
                 : "+f"(c[0]), "+f"(c[1]), "+f"(c[2]), "+f"(c[3])
                 : "r"(a[0]), "r"(a[1]), "r"(a[2]), "r"(a[3]), "r"(b[0]), "r"(b[1]));
}

// smem layout (bytes): padded stride 40 bf16 (80B = 5 granules) per row
#define S_AH 0
#define S_AL 10240
#define S_BH 20480
#define S_BL 25600
#define S_STAGE 30720
#define S_TOTAL 61440

// ---------------------------------------------------------------------------
// Kernel 0: expand + bf16-split W -> [m][k] row-major
// ---------------------------------------------------------------------------
__global__ void expand_w_kernel(const float* __restrict__ w_v,
                                const float* __restrict__ w1) {
    int idx = blockIdx.x * 256 + threadIdx.x;
    if (idx >= MROWS * KIN) return;
    int m = idx >> 9, k = idx & 511;
    int i = k >> 3, f = k & 7;
    float val;
    if (m < 512) {
        int o = m >> 3, g = m & 7;
        val = w_v[(o * 64 + i) * 8 + c_perm[g][f]];
    } else {
        int m2 = m - 512;
        int o = m2 >> 3, g = m2 & 7;
        val = w1[(o * 64 + i) * 8 + c_perm[g][f]];
    }
    __nv_bfloat16 h = __float2bfloat16(val);
    g_Wh[idx] = h;
    g_Wl[idx] = __float2bfloat16(val - __bfloat162float(h));
}

// ---------------------------------------------------------------------------
// Kernel 0b: transpose + bf16-split x -> [b][n][k] row-major
// grid (49 ntiles, 8 kchunks, 8 batch), 64x64 tiles
// ---------------------------------------------------------------------------
__global__ __launch_bounds__(256) void convx_kernel(const float* __restrict__ x) {
    const int nt = blockIdx.x, ck = blockIdx.y, bb = blockIdx.z;
    __shared__ float s[64][65];
    const int tid = threadIdx.x;
    const float* __restrict__ src = x + ((size_t)bb * KIN + ck * 64) * NPIX + nt * 64;
#pragma unroll
    for (int i = 0; i < 16; i++) {
        int flat = i * 256 + tid;
        int kk = flat >> 6, nn = flat & 63;
        s[kk][nn] = src[(size_t)kk * NPIX + nn];
    }
    __syncthreads();
#pragma unroll
    for (int it = 0; it < 2; it++) {
        int task = it * 256 + tid;        // 512 tasks: 64 n-rows x 8 granules
        int nn = task >> 3, g = task & 7;
        int n = nt * 64 + nn;
        uint32_t hw[4], lw[4];
#pragma unroll
        for (int j = 0; j < 4; j++) {
            float v0 = s[g * 8 + 2 * j][nn];
            float v1 = s[g * 8 + 2 * j + 1][nn];
            __nv_bfloat16 h0 = __float2bfloat16(v0), h1 = __float2bfloat16(v1);
            __nv_bfloat16 l0 = __float2bfloat16(v0 - __bfloat162float(h0));
            __nv_bfloat16 l1 = __float2bfloat16(v1 - __bfloat162float(h1));
            hw[j] = (uint32_t)__bfloat16_as_ushort(h0) | ((uint32_t)__bfloat16_as_ushort(h1) << 16);
            lw[j] = (uint32_t)__bfloat16_as_ushort(l0) | ((uint32_t)__bfloat16_as_ushort(l1) << 16);
        }
        size_t g4 = ((size_t)bb * NPIX + n) * 64 + ck * 8 + g;   // uint4 index (row=64 u4)
        ((uint4*)g_xh)[g4] = make_uint4(hw[0], hw[1], hw[2], hw[3]);
        ((uint4*)g_xl)[g4] = make_uint4(lw[0], lw[1], lw[2], lw[3]);
    }
}

// ---------------------------------------------------------------------------
// Kernel 1: bf16-split mma.sync GEMM.
// C[768 x 3136] = W[768 x 512] @ X[512 x 3136] per batch.
// CTA 256 thr (8 warps 4Mx2N), tile 128M x 64N, BK=32 double-buffered.
// D += Ah*Bh + Ah*Bl + Al*Bh (fp32 accum).
// ---------------------------------------------------------------------------
__global__ __launch_bounds__(256) void gemm_mma_kernel() {
    extern __shared__ char sm[];
    const uint32_t sb = smem_u32(sm);
    const int tid = threadIdx.x;
    const int lane = tid & 31, wid = tid >> 5;
    const int warpM = wid >> 1, warpN = wid & 1;
    const int bx = blockIdx.x, bm = blockIdx.y, bb = blockIdx.z;
    const int n0 = bx * 64;

    const uint4* __restrict__ gAh = ((const uint4*)g_Wh) + (size_t)bm * 128 * 64;
    const uint4* __restrict__ gAl = ((const uint4*)g_Wl) + (size_t)bm * 128 * 64;
    const uint4* __restrict__ gBh = ((const uint4*)g_xh) + ((size_t)bb * NPIX + n0) * 64;
    const uint4* __restrict__ gBl = ((const uint4*)g_xl) + ((size_t)bb * NPIX + n0) * 64;

    // per-thread load slots
    const int aml0 = tid >> 2, ag = tid & 3;       // A rows tid>>2 and +64, granule 0..3
    const int bn = tid >> 2, bg = tid & 3;         // B row, granule

    uint4 pA0, pA1, pL0, pL1, pB, pQ;

#define PREFETCH(ck) do { \
        pA0 = gAh[(size_t)aml0 * 64 + (ck) * 4 + ag]; \
        pA1 = gAh[(size_t)(aml0 + 64) * 64 + (ck) * 4 + ag]; \
        pL0 = gAl[(size_t)aml0 * 64 + (ck) * 4 + ag]; \
        pL1 = gAl[(size_t)(aml0 + 64) * 64 + (ck) * 4 + ag]; \
        pB  = gBh[(size_t)bn * 64 + (ck) * 4 + bg]; \
        pQ  = gBl[(size_t)bn * 64 + (ck) * 4 + bg]; \
    } while (0)

#define STORE(s) do { \
        char* st = sm + (s) * S_STAGE; \
        ((uint4*)(st + S_AH))[aml0 * 5 + ag] = pA0; \
        ((uint4*)(st + S_AH))[(aml0 + 64) * 5 + ag] = pA1; \
        ((uint4*)(st + S_AL))[aml0 * 5 + ag] = pL0; \
        ((uint4*)(st + S_AL))[(aml0 + 64) * 5 + ag] = pL1; \
        ((uint4*)(st + S_BH))[bn * 5 + bg] = pB; \
        ((uint4*)(st + S_BL))[bn * 5 + bg] = pQ; \
    } while (0)

    float acc[2][4][4];
#pragma unroll
    for (int ms = 0; ms < 2; ms++)
#pragma unroll
        for (int ns = 0; ns < 4; ns++)
#pragma unroll
            for (int j = 0; j < 4; j++) acc[ms][ns][j] = 0.f;

    // ldmatrix lane address components
    const int a_r = (lane & 7) + ((lane >> 3) & 1) * 8;
    const int a_c = (lane >> 4) * 8;
    const int b_r = (lane & 7) + ((lane >> 4) & 1) * 8;
    const int b_c = ((lane >> 3) & 1) * 8;

    PREFETCH(0);
    STORE(0);
    __syncthreads();

    for (int ck = 0; ck < 16; ck++) {
        const int s = ck & 1;
        if (ck + 1 < 16) PREFETCH(ck + 1);

        const uint32_t stb = sb + s * S_STAGE;
#pragma unroll
        for (int kk = 0; kk < 32; kk += 16) {
            uint32_t ah[2][4], al[2][4], bh[4][2], bl[4][2];
#pragma unroll
            for (int ms = 0; ms < 2; ms++) {
                uint32_t row = warpM * 32 + ms * 16 + a_r;
                uint32_t off = (row * 40 + kk + a_c) * 2;
                ldsm_x4(ah[ms], stb + S_AH + off);
                ldsm_x4(al[ms], stb + S_AL + off);
            }
#pragma unroll
            for (int np = 0; np < 2; np++) {
                uint32_t row = warpN * 32 + np * 16 + b_r;
                uint32_t off = (row * 40 + kk + b_c) * 2;
                uint32_t r4[4];
                ldsm_x4(r4, stb + S_BH + off);
                bh[np * 2][0] = r4[0]; bh[np * 2][1] = r4[1];
                bh[np * 2 + 1][0] = r4[2]; bh[np * 2 + 1][1] = r4[3];
                ldsm_x4(r4, stb + S_BL + off);
                bl[np * 2][0] = r4[0]; bl[np * 2][1] = r4[1];
                bl[np * 2 + 1][0] = r4[2]; bl[np * 2 + 1][1] = r4[3];
            }
#pragma unroll
            for (int ms = 0; ms < 2; ms++)
#pragma unroll
                for (int ns = 0; ns < 4; ns++) {
                    mma16816(acc[ms][ns], ah[ms], bh[ns]);
                    mma16816(acc[ms][ns], ah[ms], bl[ns]);
                    mma16816(acc[ms][ns], al[ms], bh[ns]);
                }
        }

        if (ck + 1 < 16) {
            __syncthreads();
            STORE(s ^ 1);
            __syncthreads();
        }
    }

    // writeback: frag (ms,ns): rows warpM*32+ms*16+(lane>>2) and +8,
    // cols warpN*32+ns*8+(lane&3)*2
    const int r_base = lane >> 2;
    const int c_base = (lane & 3) * 2;
#pragma unroll
    for (int ms = 0; ms < 2; ms++) {
#pragma unroll
        for (int ns = 0; ns < 4; ns++) {
            int m_loc = warpM * 32 + ms * 16 + r_base;
            int n_loc = warpN * 32 + ns * 8 + c_base;
            int m_g = bm * 128 + m_loc;
            int n_g = n0 + n_loc;
            float* dst0;
            float* dst1;
            if (bm < 4) {
                dst0 = g_xv + ((size_t)bb * CXV + m_g) * NPIX + n_g;
                dst1 = g_xv + ((size_t)bb * CXV + m_g + 8) * NPIX + n_g;
            } else {
                dst0 = g_u + ((size_t)bb * CU + (m_g - 512)) * NPIX + n_g;
                dst1 = g_u + ((size_t)bb * CU + (m_g - 512 + 8)) * NPIX + n_g;
            }
            *(float2*)dst0 = make_float2(acc[ms][ns][0], acc[ms][ns][1]);
            *(float2*)dst1 = make_float2(acc[ms][ns][2], acc[ms][ns][3]);
        }
    }
}

// ---------------------------------------------------------------------------
// Kernel 2: GroupNorm stats
// ---------------------------------------------------------------------------
__global__ __launch_bounds__(256) void stats_kernel() {
    const int bi = blockIdx.x;
    const int b = bi >> 5, i = bi & 31;
    const float* __restrict__ base = g_u + ((size_t)b * CU + i * 8) * NPIX;
    const int n = 8 * NPIX;
    float s = 0.f, s2 = 0.f;
    for (int idx = threadIdx.x; idx < n; idx += 256) {
        float v = base[idx];
        s += v;
        s2 += v * v;
    }
    __shared__ float ss[256], ss2[256];
    ss[threadIdx.x] = s;
    ss2[threadIdx.x] = s2;
    __syncthreads();
    for (int stride = 128; stride > 0; stride >>= 1) {
        if (threadIdx.x < stride) {
            ss[threadIdx.x] += ss[threadIdx.x + stride];
            ss2[threadIdx.x] += ss2[threadIdx.x + stride];
        }
        __syncthreads();
    }
    if (threadIdx.x == 0) {
        float mean = ss[0] / (float)n;
        float var = ss2[0] / (float)n - mean * mean;
        g_mean[bi] = mean;
        g_rstd[bi] = rsqrtf(var + 1e-5f);
    }
}

// ---------------------------------------------------------------------------
// Kernel 3: epilogue (unchanged from R3)
// ---------------------------------------------------------------------------
__global__ __launch_bounds__(256) void epi_kernel(const float* __restrict__ gn_gamma,
                                                  const float* __restrict__ gn_beta,
                                                  const float* __restrict__ w2,
                                                  const float* __restrict__ b2,
                                                  float* __restrict__ out) {
    const int tile = blockIdx.x;
    const int gf = blockIdx.y;
    const int bb = blockIdx.z;
    const int f = gf >> 2, G = gf & 3;
    const int ty0 = (tile >> 2) * 14;
    const int tx0 = (tile & 3) * 14;
    const int tid = threadIdx.x;

    __shared__ float xs[16][16][17];
    __shared__ float th[9][200];
    __shared__ float s_w2[9][32];
    __shared__ float s_b2[9];
    __shared__ float s_gn[32][4];

    for (int idx = tid; idx < 9 * 32; idx += 256) {
        int t = idx >> 5, i = idx & 31;
        s_w2[t][i] = w2[(G * 9 + t) * 32 + i];
    }
    if (tid < 9) s_b2[tid] = b2[G * 9 + tid];
    if (tid >= 32 && tid < 64) {
        int i = tid - 32;
        s_gn[i][0] = g_mean[bb * 32 + i];
        s_gn[i][1] = g_rstd[bb * 32 + i];
        s_gn[i][2] = gn_gamma[i * 8 + f];
        s_gn[i][3] = gn_beta[i * 8 + f];
    }
    {
        int yy = tid >> 4, xx = tid & 15;
        int gy = ty0 - 1 + yy, gx = tx0 - 1 + xx;
        bool ok = (gy >= 0 && gy < HW && gx >= 0 && gx < HW);
        size_t base = ((size_t)bb * CXV + G * 128 + f) * NPIX + gy * HW + gx;
#pragma unroll
        for (int c = 0; c < 16; c++) {
            float v = 0.f;
            if (ok) v = g_xv[base + (size_t)c * 8 * NPIX];
            xs[c][yy][xx] = v;
        }
    }
    __syncthreads();

    if (tid < 196) {
        int py = tid / 14, px = tid - py * 14;
        int p = (ty0 + py) * HW + (tx0 + px);
        float acc[9];
#pragma unroll
        for (int t = 0; t < 9; t++) acc[t] = s_b2[t];
        const float* __restrict__ ub = g_u + ((size_t)bb * CU + f) * NPIX + p;
#pragma unroll 8
        for (int i = 0; i < 32; i++) {
            float v = ub[(size_t)i * 8 * NPIX];
            v = (v - s_gn[i][0]) * s_gn[i][1] * s_gn[i][2] + s_gn[i][3];
            v = fmaxf(v, 0.f);
#pragma unroll
            for (int t = 0; t < 9; t++) acc[t] = fmaf(s_w2[t][i], v, acc[t]);
        }
#pragma unroll
        for (int t = 0; t < 9; t++) th[t][tid] = acc[t];
    }
    __syncthreads();

    if (tid < 196) {
        int py = tid / 14, px = tid - py * 14;
        float thr[9];
#pragma unroll
        for (int t = 0; t < 9; t++) thr[t] = th[c_tap[f][t]][tid];
        size_t obase = ((size_t)bb * CXV + G * 128 + f) * NPIX
                     + (ty0 + py) * HW + (tx0 + px);
#pragma unroll
        for (int c = 0; c < 16; c++) {
            float acc = 0.f;
#pragma unroll
            for (int ti = 0; ti < 3; ti++)
#pragma unroll
                for (int tj = 0; tj < 3; tj++)
                    acc = fmaf(thr[ti * 3 + tj], xs[c][py + ti][px + tj], acc);
            out[obase + (size_t)c * 8 * NPIX] = acc;
        }
    }
}

// ---------------------------------------------------------------------------
extern "C" void kernel_launch(void* const* d_in, const int* in_sizes, int n_in,
                              void* d_out, int out_size) {
    const float* x        = (const float*)d_in[0];
    const float* w_v      = (const float*)d_in[1];
    const float* w1       = (const float*)d_in[2];
    const float* gn_gamma = (const float*)d_in[3];
    const float* gn_beta  = (const float*)d_in[4];
    const float* w2       = (const float*)d_in[5];
    const float* b2       = (const float*)d_in[6];
    float* out = (float*)d_out;

    cudaFuncSetAttribute(gemm_mma_kernel,
                         cudaFuncAttributeMaxDynamicSharedMemorySize, S_TOTAL);

    expand_w_kernel<<<(MROWS * KIN + 255) / 256, 256>>>(w_v, w1);
    {
        dim3 grid(49, 8, BATCH);
        convx_kernel<<<grid, 256>>>(x);
    }
    {
        dim3 grid(49, 6, BATCH);     // (n-tile64, m-tile128, batch)
        gemm_mma_kernel<<<grid, 256, S_TOTAL>>>();
    }
    stats_kernel<<<BATCH * CMID, 256>>>();
    {
        dim3 grid(16, 32, BATCH);
        epi_kernel<<<grid, 256>>>(gn_gamma, gn_beta, w2, b2, out);
    }
}